// round 2
// baseline (speedup 1.0000x reference)
#include <cuda_runtime.h>
#include <cuda_fp16.h>
#include <mma.h>

using namespace nvcuda;

#define V_N 20000
#define E_N 40000
#define NIN 74
#define EIN 12
#define D 64
#define EH 128
#define DD 4096     // D*D
#define STEPS 6

// ---------------- scratch (static device globals; no allocs allowed) --------
__device__ float  d_h[V_N * D];                // node hidden state (fp32)
__device__ float  d_neigh[V_N * D];            // scatter accumulator
__device__ __half d_z[E_N * EH];               // edge hidden (fp16, GEMM A)
__device__ __half d_W2T[EH * DD];              // en_W2 transposed fp16 (GEMM B)
__device__ __half d_ew[(size_t)E_N * DD];      // per-edge 64x64 weights, fp16
__device__ float  d_WT[D * 6 * D];             // [64][384] transposed GRU weights

// ---------------- prep kernels ----------------------------------------------
__global__ void prep_w2t(const float* __restrict__ W2) {
    int idx = blockIdx.x * blockDim.x + threadIdx.x;   // k*4096 + n
    if (idx >= EH * DD) return;
    int k = idx >> 12, n = idx & (DD - 1);
    d_W2T[idx] = __float2half(W2[n * EH + k]);
}

__global__ void prep_wt(const float* __restrict__ Wih, const float* __restrict__ Whh) {
    int idx = blockIdx.x * blockDim.x + threadIdx.x;   // k*384 + j
    if (idx >= D * 384) return;
    int k = idx / 384, j = idx % 384;
    d_WT[idx] = (j < 192) ? Wih[j * D + k] : Whh[(j - 192) * D + k];
}

// h = relu(node_feats @ proj_W^T + b)
__global__ void proj_kernel(const float* __restrict__ nf,
                            const float* __restrict__ W,
                            const float* __restrict__ b) {
    int idx = blockIdx.x * blockDim.x + threadIdx.x;
    if (idx >= V_N * D) return;
    int v = idx >> 6, o = idx & 63;
    const float* nr = nf + v * NIN;
    const float* wr = W  + o * NIN;
    float acc = b[o];
    #pragma unroll
    for (int i = 0; i < NIN; i++) acc = fmaf(nr[i], wr[i], acc);
    d_h[idx] = fmaxf(acc, 0.f);
}

// z = relu(edge_feats @ en_W1^T + b1)  -> fp16
__global__ void zhid_kernel(const float* __restrict__ ef,
                            const float* __restrict__ W1,
                            const float* __restrict__ b1) {
    int idx = blockIdx.x * blockDim.x + threadIdx.x;
    if (idx >= E_N * EH) return;
    int e = idx >> 7, k = idx & 127;
    const float* er = ef + e * EIN;
    const float* wr = W1 + k * EIN;
    float acc = b1[k];
    #pragma unroll
    for (int i = 0; i < EIN; i++) acc = fmaf(er[i], wr[i], acc);
    d_z[idx] = __float2half(fmaxf(acc, 0.f));
}

// ---------------- ew GEMM: (E x 128) @ (128 x 4096) + b2 -> fp16 ------------
// block = 128 threads (4 warps), tile 64(M) x 64(N), K=128 in chunks of 16
__global__ void ew_gemm(const float* __restrict__ b2) {
    __shared__ __half As[64][16];
    __shared__ __half Bs[16][64];
    __shared__ float  Cs[64][64];

    const int m0 = blockIdx.x * 64;   // edge rows
    const int n0 = blockIdx.y * 64;   // output cols
    const int tid = threadIdx.x;
    const int warp = tid >> 5;

    wmma::fragment<wmma::accumulator, 16, 16, 16, float> acc[4];
    #pragma unroll
    for (int n = 0; n < 4; n++) wmma::fill_fragment(acc[n], 0.f);

    for (int kt = 0; kt < EH; kt += 16) {
        {   // A: 64 rows x 16 halves; thread: row=tid>>1, 8-half chunk
            int r = tid >> 1, c = (tid & 1) * 8;
            *(int4*)&As[r][c] = *(const int4*)&d_z[(size_t)(m0 + r) * EH + kt + c];
        }
        {   // B: 16 rows x 64 halves
            int r = tid >> 3, c = (tid & 7) * 8;
            *(int4*)&Bs[r][c] = *(const int4*)&d_W2T[(size_t)(kt + r) * DD + n0 + c];
        }
        __syncthreads();
        wmma::fragment<wmma::matrix_a, 16, 16, 16, __half, wmma::row_major> afr;
        wmma::load_matrix_sync(afr, &As[warp * 16][0], 16);
        #pragma unroll
        for (int n = 0; n < 4; n++) {
            wmma::fragment<wmma::matrix_b, 16, 16, 16, __half, wmma::row_major> bfr;
            wmma::load_matrix_sync(bfr, &Bs[0][n * 16], 64);
            wmma::mma_sync(acc[n], afr, bfr, acc[n]);
        }
        __syncthreads();
    }
    #pragma unroll
    for (int n = 0; n < 4; n++)
        wmma::store_matrix_sync(&Cs[warp * 16][n * 16], acc[n], 64, wmma::mem_row_major);
    __syncthreads();

    // epilogue: add bias, convert to fp16, 16B stores
    for (int s = tid; s < 512; s += 128) {
        int r = s >> 3, c8 = (s & 7) * 8;
        __half tmp[8];
        #pragma unroll
        for (int q = 0; q < 8; q++)
            tmp[q] = __float2half(Cs[r][c8 + q] + b2[n0 + c8 + q]);
        *(int4*)&d_ew[(size_t)(m0 + r) * DD + n0 + c8] = *(int4*)tmp;
    }
}

// ---------------- per-step kernels -------------------------------------------
__global__ void zero_neigh() {
    int idx = blockIdx.x * blockDim.x + threadIdx.x;
    if (idx < V_N * D / 4)
        ((float4*)d_neigh)[idx] = make_float4(0.f, 0.f, 0.f, 0.f);
}

// warp per edge: m_e = h[src_e] @ ew_e ; atomic scatter into neigh[dst_e]
__global__ void scatter_kernel(const int* __restrict__ src, const int* __restrict__ dst) {
    int wg   = (blockIdx.x * blockDim.x + threadIdx.x) >> 5;
    int lane = threadIdx.x & 31;
    if (wg >= E_N) return;
    int se = src[wg], de = dst[wg];
    float2 hv = ((const float2*)(d_h + (size_t)se * D))[lane];
    const __half2* W = (const __half2*)(d_ew + (size_t)wg * DD);
    float accx = 0.f, accy = 0.f;
    #pragma unroll
    for (int p = 0; p < 32; p++) {
        float hx = __shfl_sync(0xffffffffu, hv.x, p);
        float hy = __shfl_sync(0xffffffffu, hv.y, p);
        float2 r0 = __half22float2(W[(2 * p)     * 32 + lane]);
        float2 r1 = __half22float2(W[(2 * p + 1) * 32 + lane]);
        accx = fmaf(hx, r0.x, accx); accy = fmaf(hx, r0.y, accy);
        accx = fmaf(hy, r1.x, accx); accy = fmaf(hy, r1.y, accy);
    }
    atomicAdd(&d_neigh[(size_t)de * D + 2 * lane],     accx);
    atomicAdd(&d_neigh[(size_t)de * D + 2 * lane + 1], accy);
}

// GRU update: block=128 threads, 8 nodes/block, 4 nodes register-blocked/thread
__global__ void gru_kernel(const float* __restrict__ conv_b,
                           const float* __restrict__ bih,
                           const float* __restrict__ bhh) {
    __shared__ float xs[8][D];
    __shared__ float hs[8][D];
    const int nb = blockIdx.x * 8;
    const int tid = threadIdx.x;

    for (int i = tid; i < 8 * D; i += 128) {
        int nn = i >> 6, k = i & 63;
        int node = nb + nn;
        xs[nn][k] = fmaxf(d_neigh[(size_t)node * D + k] + conv_b[k], 0.f);
        hs[nn][k] = d_h[(size_t)node * D + k];
    }
    __syncthreads();

    const int j = tid & 63;
    const int q = tid >> 6;   // node quartet 0/1
    float air[4] = {0,0,0,0}, aiz[4] = {0,0,0,0}, ain[4] = {0,0,0,0};
    float ahr[4] = {0,0,0,0}, ahz[4] = {0,0,0,0}, ahn[4] = {0,0,0,0};

    #pragma unroll 4
    for (int k = 0; k < D; k++) {
        const float* wr = d_WT + k * 384;
        float w0 = wr[j], w1 = wr[64 + j], w2 = wr[128 + j];
        float w3 = wr[192 + j], w4 = wr[256 + j], w5 = wr[320 + j];
        #pragma unroll
        for (int nn = 0; nn < 4; nn++) {
            float xv = xs[q * 4 + nn][k];
            float hv = hs[q * 4 + nn][k];
            air[nn] = fmaf(w0, xv, air[nn]);
            aiz[nn] = fmaf(w1, xv, aiz[nn]);
            ain[nn] = fmaf(w2, xv, ain[nn]);
            ahr[nn] = fmaf(w3, hv, ahr[nn]);
            ahz[nn] = fmaf(w4, hv, ahz[nn]);
            ahn[nn] = fmaf(w5, hv, ahn[nn]);
        }
    }
    float br = bih[j], bz = bih[64 + j], bn = bih[128 + j];
    float cr = bhh[j], cz = bhh[64 + j], cn = bhh[128 + j];
    #pragma unroll
    for (int nn = 0; nn < 4; nn++) {
        float r  = 1.f / (1.f + expf(-(air[nn] + br + ahr[nn] + cr)));
        float zg = 1.f / (1.f + expf(-(aiz[nn] + bz + ahz[nn] + cz)));
        float n  = tanhf(ain[nn] + bn + r * (ahn[nn] + cn));
        float hp = hs[q * 4 + nn][j];
        d_h[(size_t)(nb + q * 4 + nn) * D + j] = (1.f - zg) * n + zg * hp;
    }
}

// ---------------- predictor: warp per edge ----------------------------------
__global__ void pred_kernel(const int* __restrict__ src, const int* __restrict__ dst,
                            const float* __restrict__ pW, const float* __restrict__ pb,
                            float* __restrict__ out) {
    int wg   = (blockIdx.x * blockDim.x + threadIdx.x) >> 5;
    int lane = threadIdx.x & 31;
    if (wg >= E_N) return;
    int se = src[wg], de = dst[wg];
    float2 a  = ((const float2*)(d_h + (size_t)se * D))[lane];
    float2 b  = ((const float2*)(d_h + (size_t)de * D))[lane];
    float2 w1 = ((const float2*)pW)[lane];
    float2 w2 = ((const float2*)pW)[32 + lane];
    float acc = a.x * w1.x + a.y * w1.y + b.x * w2.x + b.y * w2.y;
    #pragma unroll
    for (int off = 16; off > 0; off >>= 1)
        acc += __shfl_down_sync(0xffffffffu, acc, off);
    if (lane == 0) out[wg] = acc + pb[0];
}

// ---------------- launch ------------------------------------------------------
extern "C" void kernel_launch(void* const* d_in, const int* in_sizes, int n_in,
                              void* d_out, int out_size) {
    const float* node_feats = (const float*)d_in[0];
    const float* edge_feats = (const float*)d_in[1];
    const int*   src        = (const int*)d_in[2];
    const int*   dst        = (const int*)d_in[3];
    const float* proj_W     = (const float*)d_in[4];
    const float* proj_b     = (const float*)d_in[5];
    const float* en_W1      = (const float*)d_in[6];
    const float* en_b1      = (const float*)d_in[7];
    const float* en_W2      = (const float*)d_in[8];
    const float* en_b2      = (const float*)d_in[9];
    const float* conv_b     = (const float*)d_in[10];
    const float* gru_Wih    = (const float*)d_in[11];
    const float* gru_Whh    = (const float*)d_in[12];
    const float* gru_bih    = (const float*)d_in[13];
    const float* gru_bhh    = (const float*)d_in[14];
    const float* pred_W     = (const float*)d_in[15];
    const float* pred_b     = (const float*)d_in[16];
    float* out = (float*)d_out;

    prep_w2t<<<(EH * DD + 255) / 256, 256>>>(en_W2);
    prep_wt<<<(D * 384 + 255) / 256, 256>>>(gru_Wih, gru_Whh);
    proj_kernel<<<(V_N * D + 255) / 256, 256>>>(node_feats, proj_W, proj_b);
    zhid_kernel<<<(E_N * EH + 255) / 256, 256>>>(edge_feats, en_W1, en_b1);

    dim3 gg(E_N / 64, DD / 64);
    ew_gemm<<<gg, 128>>>(en_b2);

    for (int s = 0; s < STEPS; s++) {
        zero_neigh<<<(V_N * D / 4 + 255) / 256, 256>>>();
        scatter_kernel<<<E_N / 8, 256>>>(src, dst);
        gru_kernel<<<V_N / 8, 128>>>(conv_b, gru_bih, gru_bhh);
    }
    pred_kernel<<<E_N / 8, 256>>>(src, dst, pred_W, pred_b, out);
}

// round 3
// speedup vs baseline: 1.7143x; 1.7143x over previous
#include <cuda_runtime.h>
#include <cuda_fp16.h>
#include <mma.h>

using namespace nvcuda;

#define V_N 20000
#define E_N 40000
#define NIN 74
#define EIN 12
#define D 64
#define EH 128
#define DD 4096     // D*D
#define STEPS 6

// ---------------- scratch (static device globals; no allocs allowed) --------
__device__ float  d_h[V_N * D];                // node hidden state (fp32)
__device__ float  d_neigh[V_N * D];            // scatter accumulator
__device__ __half d_z[E_N * EH];               // edge hidden (fp16, GEMM A)
__device__ __half d_W2T[EH * DD];              // en_W2 transposed fp16 (GEMM B)
__device__ __half d_ew[(size_t)E_N * DD];      // per-edge 64x64 weights, fp16
__device__ float  d_WT[D * 6 * D];             // [64][384] transposed GRU weights

// ---------------- prep kernels ----------------------------------------------
__global__ void prep_w2t(const float* __restrict__ W2) {
    int idx = blockIdx.x * blockDim.x + threadIdx.x;   // k*4096 + n
    if (idx >= EH * DD) return;
    int k = idx >> 12, n = idx & (DD - 1);
    d_W2T[idx] = __float2half(W2[n * EH + k]);
}

__global__ void prep_wt(const float* __restrict__ Wih, const float* __restrict__ Whh) {
    int idx = blockIdx.x * blockDim.x + threadIdx.x;   // k*384 + j
    if (idx >= D * 384) return;
    int k = idx / 384, j = idx % 384;
    d_WT[idx] = (j < 192) ? Wih[j * D + k] : Whh[(j - 192) * D + k];
}

// h = relu(node_feats @ proj_W^T + b); 16 nodes per block, W staged transposed
__global__ void proj_kernel(const float* __restrict__ nf,
                            const float* __restrict__ W,
                            const float* __restrict__ b) {
    __shared__ float Ws[NIN][D];      // [i][o]
    __shared__ float nfs[16][NIN + 2];
    __shared__ float bs[D];
    const int tid = threadIdx.x;
    const int v0 = blockIdx.x * 16;

    for (int idx = tid; idx < D * NIN; idx += 256) {
        int o = idx / NIN, i = idx % NIN;
        Ws[i][o] = W[idx];
    }
    for (int idx = tid; idx < 16 * NIN; idx += 256) {
        int n = idx / NIN, i = idx % NIN;
        nfs[n][i] = nf[(size_t)(v0 + n) * NIN + i];
    }
    if (tid < D) bs[tid] = b[tid];
    __syncthreads();

    const int o = tid & 63;
    const int g = tid >> 6;     // 4 groups x 4 nodes
    #pragma unroll
    for (int nn = 0; nn < 4; nn++) {
        int n = g * 4 + nn;
        float acc = bs[o];
        #pragma unroll
        for (int i = 0; i < NIN; i++) acc = fmaf(Ws[i][o], nfs[n][i], acc);
        d_h[(size_t)(v0 + n) * D + o] = fmaxf(acc, 0.f);
    }
}

// z = relu(edge_feats @ en_W1^T + b1) -> fp16; 16 edges per block
__global__ void zhid_kernel(const float* __restrict__ ef,
                            const float* __restrict__ W1,
                            const float* __restrict__ b1) {
    __shared__ float W1s[EIN][EH];    // [i][k]
    __shared__ float b1s[EH];
    __shared__ float efs[16][EIN];
    const int tid = threadIdx.x;
    const int e0 = blockIdx.x * 16;

    for (int idx = tid; idx < EH * EIN; idx += 256) {
        int k = idx / EIN, i = idx % EIN;
        W1s[i][k] = W1[idx];
    }
    for (int idx = tid; idx < 16 * EIN; idx += 256) {
        int e = idx / EIN, i = idx % EIN;
        efs[e][i] = ef[(size_t)(e0 + e) * EIN + i];
    }
    if (tid < EH) b1s[tid] = b1[tid];
    __syncthreads();

    const int k = tid & 127;
    const int g = tid >> 7;    // 2 groups x 8 edges
    #pragma unroll
    for (int ee = 0; ee < 8; ee++) {
        int e = g * 8 + ee;
        float acc = b1s[k];
        #pragma unroll
        for (int i = 0; i < EIN; i++) acc = fmaf(W1s[i][k], efs[e][i], acc);
        d_z[(size_t)(e0 + e) * EH + k] = __float2half(fmaxf(acc, 0.f));
    }
}

// ---------------- ew GEMM: B-stationary persistent tiles ---------------------
// grid = (16 N-slabs of 256) x (25 M-slabs of 1600 edges); block = 256 (8 warps 4x2)
#define BN 256
#define BSTR 264        // half stride for Bs
#define ASTR 136        // half stride for As
#define CSTR 264        // float stride for Cs
#define MT_PER 25       // 25 tiles of 64 rows = 1600 edges per block
#define EW_B_BYTES  (EH * BSTR * 2)                 // 67584
#define EW_BIAS_OFF EW_B_BYTES
#define EW_UNI_OFF  (EW_B_BYTES + 1024)             // 68608
#define EW_SMEM     (EW_UNI_OFF + 32 * CSTR * 4)    // 68608 + 33792 = 102400

__global__ __launch_bounds__(256, 2) void ew_gemm(const float* __restrict__ b2) {
    extern __shared__ char smem[];
    __half* Bs     = (__half*)smem;
    float*  bias_s = (float*)(smem + EW_BIAS_OFF);
    __half* As     = (__half*)(smem + EW_UNI_OFF);
    float*  Cs     = (float*)(smem + EW_UNI_OFF);

    const int tid = threadIdx.x;
    const int w   = tid >> 5;
    const int wm  = w & 3;        // row group (16 rows)
    const int wn  = w >> 2;       // col group (128 cols)
    const int n0  = blockIdx.x * BN;
    const int e0  = blockIdx.y * (MT_PER * 64);

    // load B slab 128x256 (once) + bias
    for (int q = tid; q < 4096; q += 256) {
        int k = q >> 5, c8 = (q & 31) * 8;
        *(int4*)&Bs[k * BSTR + c8] = *(const int4*)&d_W2T[(size_t)k * DD + n0 + c8];
    }
    bias_s[tid] = b2[n0 + tid];

    for (int mt = 0; mt < MT_PER; mt++) {
        const int m0 = e0 + mt * 64;
        __syncthreads();   // As region free (prev epilogue done); 1st iter: no-op
        for (int q = tid; q < 1024; q += 256) {
            int r = q >> 4, c8 = (q & 15) * 8;
            *(int4*)&As[r * ASTR + c8] = *(const int4*)&d_z[(size_t)(m0 + r) * EH + c8];
        }
        __syncthreads();   // A (and, 1st iter, B) ready

        wmma::fragment<wmma::accumulator, 16, 16, 16, float> acc[8];
        #pragma unroll
        for (int f = 0; f < 8; f++) wmma::fill_fragment(acc[f], 0.f);

        #pragma unroll
        for (int kc = 0; kc < 8; kc++) {
            wmma::fragment<wmma::matrix_a, 16, 16, 16, __half, wmma::row_major> afr;
            wmma::load_matrix_sync(afr, &As[wm * 16 * ASTR + kc * 16], ASTR);
            #pragma unroll
            for (int f = 0; f < 8; f++) {
                wmma::fragment<wmma::matrix_b, 16, 16, 16, __half, wmma::row_major> bfr;
                wmma::load_matrix_sync(bfr, &Bs[kc * 16 * BSTR + wn * 128 + f * 16], BSTR);
                wmma::mma_sync(acc[f], afr, bfr, acc[f]);
            }
        }

        // epilogue in 2 half-passes (32 rows) through the As/Cs union buffer
        #pragma unroll
        for (int p = 0; p < 2; p++) {
            __syncthreads();
            if ((wm >> 1) == p) {
                int lr = (wm - 2 * p) * 16;
                #pragma unroll
                for (int f = 0; f < 8; f++)
                    wmma::store_matrix_sync(&Cs[lr * CSTR + wn * 128 + f * 16],
                                            acc[f], CSTR, wmma::mem_row_major);
            }
            __syncthreads();
            for (int q = tid; q < 1024; q += 256) {
                int r = q >> 5, c8 = (q & 31) * 8;
                __half tmp[8];
                #pragma unroll
                for (int j = 0; j < 8; j++)
                    tmp[j] = __float2half(Cs[r * CSTR + c8 + j] + bias_s[c8 + j]);
                *(int4*)&d_ew[(size_t)(m0 + p * 32 + r) * DD + n0 + c8] = *(int4*)tmp;
            }
        }
    }
}

// ---------------- per-step kernels -------------------------------------------
__global__ void zero_neigh() {
    int idx = blockIdx.x * blockDim.x + threadIdx.x;
    if (idx < V_N * D / 4)
        ((float4*)d_neigh)[idx] = make_float4(0.f, 0.f, 0.f, 0.f);
}

// warp per edge: m_e = h[src_e] @ ew_e ; atomic scatter into neigh[dst_e]
__global__ void scatter_kernel(const int* __restrict__ src, const int* __restrict__ dst) {
    int wg   = (blockIdx.x * blockDim.x + threadIdx.x) >> 5;
    int lane = threadIdx.x & 31;
    if (wg >= E_N) return;
    int se = __ldg(&src[wg]), de = __ldg(&dst[wg]);
    float2 hv = ((const float2*)(d_h + (size_t)se * D))[lane];
    const __half2* W = (const __half2*)(d_ew + (size_t)wg * DD);
    float accx = 0.f, accy = 0.f;
    #pragma unroll
    for (int p = 0; p < 32; p++) {
        float hx = __shfl_sync(0xffffffffu, hv.x, p);
        float hy = __shfl_sync(0xffffffffu, hv.y, p);
        float2 r0 = __half22float2(W[(2 * p)     * 32 + lane]);
        float2 r1 = __half22float2(W[(2 * p + 1) * 32 + lane]);
        accx = fmaf(hx, r0.x, accx); accy = fmaf(hx, r0.y, accy);
        accx = fmaf(hy, r1.x, accx); accy = fmaf(hy, r1.y, accy);
    }
    atomicAdd(&d_neigh[(size_t)de * D + 2 * lane],     accx);
    atomicAdd(&d_neigh[(size_t)de * D + 2 * lane + 1], accy);
}

// GRU update: block=128 threads, 8 nodes/block, 4 nodes register-blocked/thread
__global__ void gru_kernel(const float* __restrict__ conv_b,
                           const float* __restrict__ bih,
                           const float* __restrict__ bhh) {
    __shared__ float xs[8][D];
    __shared__ float hs[8][D];
    const int nb = blockIdx.x * 8;
    const int tid = threadIdx.x;

    for (int i = tid; i < 8 * D; i += 128) {
        int nn = i >> 6, k = i & 63;
        int node = nb + nn;
        xs[nn][k] = fmaxf(d_neigh[(size_t)node * D + k] + conv_b[k], 0.f);
        hs[nn][k] = d_h[(size_t)node * D + k];
    }
    __syncthreads();

    const int j = tid & 63;
    const int q = tid >> 6;
    float air[4] = {0,0,0,0}, aiz[4] = {0,0,0,0}, ain[4] = {0,0,0,0};
    float ahr[4] = {0,0,0,0}, ahz[4] = {0,0,0,0}, ahn[4] = {0,0,0,0};

    #pragma unroll 4
    for (int k = 0; k < D; k++) {
        const float* wr = d_WT + k * 384;
        float w0 = wr[j], w1 = wr[64 + j], w2 = wr[128 + j];
        float w3 = wr[192 + j], w4 = wr[256 + j], w5 = wr[320 + j];
        #pragma unroll
        for (int nn = 0; nn < 4; nn++) {
            float xv = xs[q * 4 + nn][k];
            float hv = hs[q * 4 + nn][k];
            air[nn] = fmaf(w0, xv, air[nn]);
            aiz[nn] = fmaf(w1, xv, aiz[nn]);
            ain[nn] = fmaf(w2, xv, ain[nn]);
            ahr[nn] = fmaf(w3, hv, ahr[nn]);
            ahz[nn] = fmaf(w4, hv, ahz[nn]);
            ahn[nn] = fmaf(w5, hv, ahn[nn]);
        }
    }
    float br = bih[j], bz = bih[64 + j], bn = bih[128 + j];
    float cr = bhh[j], cz = bhh[64 + j], cn = bhh[128 + j];
    #pragma unroll
    for (int nn = 0; nn < 4; nn++) {
        float r  = 1.f / (1.f + expf(-(air[nn] + br + ahr[nn] + cr)));
        float zg = 1.f / (1.f + expf(-(aiz[nn] + bz + ahz[nn] + cz)));
        float n  = tanhf(ain[nn] + bn + r * (ahn[nn] + cn));
        float hp = hs[q * 4 + nn][j];
        d_h[(size_t)(nb + q * 4 + nn) * D + j] = (1.f - zg) * n + zg * hp;
    }
}

// ---------------- predictor: warp per edge ----------------------------------
__global__ void pred_kernel(const int* __restrict__ src, const int* __restrict__ dst,
                            const float* __restrict__ pW, const float* __restrict__ pb,
                            float* __restrict__ out) {
    int wg   = (blockIdx.x * blockDim.x + threadIdx.x) >> 5;
    int lane = threadIdx.x & 31;
    if (wg >= E_N) return;
    int se = src[wg], de = dst[wg];
    float2 a  = ((const float2*)(d_h + (size_t)se * D))[lane];
    float2 b  = ((const float2*)(d_h + (size_t)de * D))[lane];
    float2 w1 = ((const float2*)pW)[lane];
    float2 w2 = ((const float2*)pW)[32 + lane];
    float acc = a.x * w1.x + a.y * w1.y + b.x * w2.x + b.y * w2.y;
    #pragma unroll
    for (int off = 16; off > 0; off >>= 1)
        acc += __shfl_down_sync(0xffffffffu, acc, off);
    if (lane == 0) out[wg] = acc + pb[0];
}

// ---------------- launch ------------------------------------------------------
extern "C" void kernel_launch(void* const* d_in, const int* in_sizes, int n_in,
                              void* d_out, int out_size) {
    const float* node_feats = (const float*)d_in[0];
    const float* edge_feats = (const float*)d_in[1];
    const int*   src        = (const int*)d_in[2];
    const int*   dst        = (const int*)d_in[3];
    const float* proj_W     = (const float*)d_in[4];
    const float* proj_b     = (const float*)d_in[5];
    const float* en_W1      = (const float*)d_in[6];
    const float* en_b1      = (const float*)d_in[7];
    const float* en_W2      = (const float*)d_in[8];
    const float* en_b2      = (const float*)d_in[9];
    const float* conv_b     = (const float*)d_in[10];
    const float* gru_Wih    = (const float*)d_in[11];
    const float* gru_Whh    = (const float*)d_in[12];
    const float* gru_bih    = (const float*)d_in[13];
    const float* gru_bhh    = (const float*)d_in[14];
    const float* pred_W     = (const float*)d_in[15];
    const float* pred_b     = (const float*)d_in[16];
    float* out = (float*)d_out;

    cudaFuncSetAttribute(ew_gemm, cudaFuncAttributeMaxDynamicSharedMemorySize, EW_SMEM);

    prep_w2t<<<(EH * DD + 255) / 256, 256>>>(en_W2);
    prep_wt<<<(D * 384 + 255) / 256, 256>>>(gru_Wih, gru_Whh);
    proj_kernel<<<V_N / 16, 256>>>(node_feats, proj_W, proj_b);
    zhid_kernel<<<E_N / 16, 256>>>(edge_feats, en_W1, en_b1);

    dim3 gg(DD / BN, E_N / (MT_PER * 64));   // (16, 25)
    ew_gemm<<<gg, 256, EW_SMEM>>>(en_b2);

    for (int s = 0; s < STEPS; s++) {
        zero_neigh<<<(V_N * D / 4 + 255) / 256, 256>>>();
        scatter_kernel<<<E_N / 8, 256>>>(src, dst);
        gru_kernel<<<V_N / 8, 128>>>(conv_b, gru_bih, gru_bhh);
    }
    pred_kernel<<<E_N / 8, 256>>>(src, dst, pred_W, pred_b, out);
}

// round 6
// speedup vs baseline: 1.7843x; 1.0408x over previous
#include <cuda_runtime.h>
#include <cuda_fp16.h>
#include <mma.h>
#include <cstdint>

using namespace nvcuda;

#define V_N 20000
#define V_PAD 20032      // 313 * 64
#define E_N 40000
#define E_PAD 40064      // 313 * 128
#define NT 313           // 128-row M tiles in ew gemm
#define NIN 74
#define EIN 12
#define D 64
#define EH 128
#define DD 4096
#define STEPS 6

// ---------------- scratch (static device globals; zero-initialized) ---------
__device__ float  d_h[V_PAD * D];
__device__ float  d_neigh[V_PAD * D];
__device__ __half d_z[E_PAD * EH];
__device__ __half d_ew[(size_t)E_PAD * DD];
__device__ __half d_Wg[256 * EH];              // packed GRU weights (fp16)

// ---------------- cp.async helpers ------------------------------------------
__device__ __forceinline__ uint32_t smem_u32(const void* p) {
    uint32_t a;
    asm("{ .reg .u64 t; cvta.to.shared.u64 t, %1; cvt.u32.u64 %0, t; }" : "=r"(a) : "l"(p));
    return a;
}
__device__ __forceinline__ void cp16(uint32_t s, const void* g) {
    asm volatile("cp.async.cg.shared.global [%0], [%1], 16;" :: "r"(s), "l"(g));
}
#define CP_COMMIT() asm volatile("cp.async.commit_group;" ::: "memory")
#define CP_WAIT0()  asm volatile("cp.async.wait_group 0;" ::: "memory")

// ---------------- prep / small kernels ---------------------------------------
// pack GRU weights: Wg[256][128]; rows 0:64 [Wih_r|Whh_r], 64:128 [Wih_z|Whh_z],
// 128:192 [Wih_n|0], 192:256 [0|Whh_n]
__global__ void prep_wg(const float* __restrict__ Wih, const float* __restrict__ Whh) {
    int idx = blockIdx.x * blockDim.x + threadIdx.x;
    if (idx >= 256 * EH) return;
    int r = idx >> 7, k = idx & 127;
    float v = 0.f;
    if (r < 128) {                       // r/z rows: sum-gates
        v = (k < 64) ? Wih[r * D + k] : Whh[r * D + (k - 64)];
    } else if (r < 192) {                // i_n: Wih rows 128..191
        if (k < 64) v = Wih[r * D + k];
    } else {                             // h_n: Whh rows 128..191
        if (k >= 64) v = Whh[(r - 64) * D + (k - 64)];
    }
    d_Wg[idx] = __float2half(v);
}

__global__ void proj_kernel(const float* __restrict__ nf,
                            const float* __restrict__ W,
                            const float* __restrict__ b) {
    __shared__ float Ws[NIN][D];
    __shared__ float nfs[16][NIN + 2];
    __shared__ float bs[D];
    const int tid = threadIdx.x;
    const int v0 = blockIdx.x * 16;
    for (int idx = tid; idx < D * NIN; idx += 256) {
        int o = idx / NIN, i = idx % NIN;
        Ws[i][o] = W[idx];
    }
    for (int idx = tid; idx < 16 * NIN; idx += 256) {
        int n = idx / NIN, i = idx % NIN;
        nfs[n][i] = nf[(size_t)(v0 + n) * NIN + i];
    }
    if (tid < D) bs[tid] = b[tid];
    __syncthreads();
    const int o = tid & 63, g = tid >> 6;
    #pragma unroll
    for (int nn = 0; nn < 4; nn++) {
        int n = g * 4 + nn;
        float acc = bs[o];
        #pragma unroll
        for (int i = 0; i < NIN; i++) acc = fmaf(Ws[i][o], nfs[n][i], acc);
        d_h[(size_t)(v0 + n) * D + o] = fmaxf(acc, 0.f);
    }
}

__global__ void zhid_kernel(const float* __restrict__ ef,
                            const float* __restrict__ W1,
                            const float* __restrict__ b1) {
    __shared__ float W1s[EIN][EH];
    __shared__ float b1s[EH];
    __shared__ float efs[16][EIN];
    const int tid = threadIdx.x;
    const int e0 = blockIdx.x * 16;
    for (int idx = tid; idx < EH * EIN; idx += 256) {
        int k = idx / EIN, i = idx % EIN;
        W1s[i][k] = W1[idx];
    }
    for (int idx = tid; idx < 16 * EIN; idx += 256) {
        int e = idx / EIN, i = idx % EIN;
        efs[e][i] = ef[(size_t)(e0 + e) * EIN + i];
    }
    if (tid < EH) b1s[tid] = b1[tid];
    __syncthreads();
    const int k = tid & 127, g = tid >> 7;
    #pragma unroll
    for (int ee = 0; ee < 8; ee++) {
        int e = g * 8 + ee;
        float acc = b1s[k];
        #pragma unroll
        for (int i = 0; i < EIN; i++) acc = fmaf(W1s[i][k], efs[e][i], acc);
        d_z[(size_t)(e0 + e) * EH + k] = __float2half(fmaxf(acc, 0.f));
    }
}

// ---------------- ew GEMM (WMMA, bias folded into K) --------------------------
// C[E_PAD,4096] = [z|1] @ [W2|b2]^T ; A: (m x 144) fp16, B: (n x 144) fp16 (K-major)
// block 256 thr, tile M=128 x N=128, K=144 (9 chunks); B-slab stationary.
#define ASTR 152
#define BSTR 152
#define CSTR 132
#define B_BYTES   (128 * BSTR * 2)             // 38912
#define A_BYTES   (128 * ASTR * 2)             // 38912
#define A_OFF     B_BYTES
#define C_OFF     (A_OFF + 2 * A_BYTES)        // 116736
#define EW_SMEM   (C_OFF + 64 * CSTR * 4)      // 150528
#define NSLABS 32
#define MGROUPS 4

__global__ __launch_bounds__(256) void ew_gemm(const float* __restrict__ W2,
                                               const float* __restrict__ b2) {
    extern __shared__ char smem[];
    __half* Bs = (__half*)smem;
    float*  Cs = (float*)(smem + C_OFF);
    const uint32_t sbase = smem_u32(smem);
    const int tid = threadIdx.x;
    const int w = tid >> 5;
    const int wm = w & 3;          // 4 M groups of 32 rows
    const int wn = w >> 2;         // 2 N groups of 64 cols
    const int n0 = blockIdx.x * 128;
    const int by = blockIdx.y;

    // B slab: 128 N-rows x 128 K (f32 -> f16) + bias col 128, zeros 129..143
    for (int q = tid; q < 4096; q += 256) {        // 128 rows x 32 float4
        int n = q >> 5, k4 = (q & 31) * 4;
        float4 v = *(const float4*)&W2[(size_t)(n0 + n) * EH + k4];
        __half t4[4] = { __float2half(v.x), __float2half(v.y),
                         __float2half(v.z), __float2half(v.w) };
        *(uint2*)&Bs[n * BSTR + k4] = *(uint2*)t4;
    }
    for (int q = tid; q < 2048; q += 256) {        // tails: 128 rows x 16 cols
        int n = q >> 4, k = 128 + (q & 15);
        Bs[n * BSTR + k] = (k == 128) ? __float2half(b2[n0 + n]) : __half(0);
    }
    // A-buffer constant tails (both buffers): col 128 = 1, 129..143 = 0
    for (int q = tid; q < 4096; q += 256) {
        int buf = q >> 11, r = (q >> 4) & 127, k = 128 + (q & 15);
        ((__half*)(smem + A_OFF + buf * A_BYTES))[r * ASTR + k] =
            (k == 128) ? __float2half(1.f) : __half(0);
    }
    // prefetch first A tile
    {
        uint32_t abase = sbase + A_OFF;
        for (int q = tid; q < 2048; q += 256) {    // 128 rows x 16 x 16B
            int r = q >> 4, c = (q & 15) * 8;
            cp16(abase + (uint32_t)(r * ASTR + c) * 2,
                 &d_z[(size_t)(by * 128 + r) * EH + c]);
        }
        CP_COMMIT();
    }

    const int TPT = (NT + MGROUPS - 1) / MGROUPS;
    for (int mt = 0; mt < TPT; mt++) {
        int t = by + MGROUPS * mt;
        if (t >= NT) break;
        CP_WAIT0();
        __syncthreads();

        const __half* Ab = (const __half*)(smem + A_OFF + (mt & 1) * A_BYTES);

        // prefetch next tile into other buffer (overlaps mma + epilogue)
        int tn = t + MGROUPS;
        if (tn < NT) {
            uint32_t abase = sbase + A_OFF + ((mt + 1) & 1) * A_BYTES;
            for (int q = tid; q < 2048; q += 256) {
                int r = q >> 4, c = (q & 15) * 8;
                cp16(abase + (uint32_t)(r * ASTR + c) * 2,
                     &d_z[(size_t)(tn * 128 + r) * EH + c]);
            }
            CP_COMMIT();
        }

        wmma::fragment<wmma::accumulator, 16, 16, 16, float> acc[8];
        #pragma unroll
        for (int f = 0; f < 8; f++) wmma::fill_fragment(acc[f], 0.f);

        #pragma unroll
        for (int kc = 0; kc < 9; kc++) {
            wmma::fragment<wmma::matrix_a, 16, 16, 16, __half, wmma::row_major> af[2];
            #pragma unroll
            for (int i = 0; i < 2; i++)
                wmma::load_matrix_sync(af[i], &Ab[(wm * 32 + i * 16) * ASTR + kc * 16], ASTR);
            #pragma unroll
            for (int nf = 0; nf < 4; nf++) {
                wmma::fragment<wmma::matrix_b, 16, 16, 16, __half, wmma::col_major> bf;
                wmma::load_matrix_sync(bf, &Bs[(wn * 64 + nf * 16) * BSTR + kc * 16], BSTR);
                #pragma unroll
                for (int i = 0; i < 2; i++)
                    wmma::mma_sync(acc[i * 4 + nf], af[i], bf, acc[i * 4 + nf]);
            }
        }

        // epilogue: 2 passes of 64 rows through Cs
        #pragma unroll
        for (int p = 0; p < 2; p++) {
            __syncthreads();
            if ((wm >> 1) == p) {
                int lb = (wm & 1) * 32;
                #pragma unroll
                for (int i = 0; i < 2; i++)
                    #pragma unroll
                    for (int nf = 0; nf < 4; nf++)
                        wmma::store_matrix_sync(&Cs[(lb + i * 16) * CSTR + wn * 64 + nf * 16],
                                                acc[i * 4 + nf], CSTR, wmma::mem_row_major);
            }
            __syncthreads();
            for (int q = tid; q < 1024; q += 256) {    // 64 rows x 16 int4
                int r = q >> 4, c8 = (q & 15) * 8;
                __half tmp[8];
                #pragma unroll
                for (int j = 0; j < 8; j++)
                    tmp[j] = __float2half(Cs[r * CSTR + c8 + j]);
                *(int4*)&d_ew[(size_t)(t * 128 + p * 64 + r) * DD + n0 + c8] = *(int4*)tmp;
            }
        }
    }
}

// ---------------- per-step kernels -------------------------------------------
__global__ void zero_neigh() {
    int idx = blockIdx.x * blockDim.x + threadIdx.x;
    if (idx < V_PAD * D / 4)
        ((float4*)d_neigh)[idx] = make_float4(0.f, 0.f, 0.f, 0.f);
}

__global__ void scatter_kernel(const int* __restrict__ src, const int* __restrict__ dst) {
    int wg   = (blockIdx.x * blockDim.x + threadIdx.x) >> 5;
    int lane = threadIdx.x & 31;
    if (wg >= E_N) return;
    int se = __ldg(&src[wg]), de = __ldg(&dst[wg]);
    float2 hv = ((const float2*)(d_h + (size_t)se * D))[lane];
    const __half2* W = (const __half2*)(d_ew + (size_t)wg * DD);
    float accx = 0.f, accy = 0.f;
    #pragma unroll
    for (int p = 0; p < 32; p++) {
        float hx = __shfl_sync(0xffffffffu, hv.x, p);
        float hy = __shfl_sync(0xffffffffu, hv.y, p);
        float2 r0 = __half22float2(W[(2 * p)     * 32 + lane]);
        float2 r1 = __half22float2(W[(2 * p + 1) * 32 + lane]);
        accx = fmaf(hx, r0.x, accx); accy = fmaf(hx, r0.y, accy);
        accx = fmaf(hy, r1.x, accx); accy = fmaf(hy, r1.y, accy);
    }
    atomicAdd(&d_neigh[(size_t)de * D + 2 * lane],     accx);
    atomicAdd(&d_neigh[(size_t)de * D + 2 * lane + 1], accy);
}

// GRU: G = [relu(neigh+cb) | h](fp16) @ Wg^T (fp32 accum), then fused gates +
// h update + neigh re-zero. block 256 thr, tile M=64 nodes x N=256 gate-rows.
#define GW_STR 136
#define GC_STR 264
#define GX_OFF (256 * GW_STR * 2)              // 69632
#define GRU_SMEM (GX_OFF + 64 * GW_STR * 2)    // 87040  (Cs 64x264x4=67584 overlays Wgs)
__global__ __launch_bounds__(256, 2) void gru_mm(const float* __restrict__ conv_b,
                                                 const float* __restrict__ bih,
                                                 const float* __restrict__ bhh) {
    extern __shared__ char smem[];
    __half* Wgs = (__half*)smem;
    __half* Xs  = (__half*)(smem + GX_OFF);
    float*  Cs  = (float*)smem;                // overlay after MMA
    const int tid = threadIdx.x;
    const int w = tid >> 5;
    const int wm = w & 1;          // 2 M groups of 32
    const int wn = w >> 1;         // 4 N groups of 64
    const int v0 = blockIdx.x * 64;

    // stage Wg 256x128
    for (int q = tid; q < 4096; q += 256) {
        int r = q >> 4, c8 = (q & 15) * 8;
        *(int4*)&Wgs[r * GW_STR + c8] = *(const int4*)&d_Wg[r * EH + c8];
    }
    // stage X: cols 0:64 relu(neigh+cb), 64:128 h
    for (int q = tid; q < 4096; q += 256) {
        int r = q >> 6, k = q & 63;
        float xv = fmaxf(d_neigh[(size_t)(v0 + r) * D + k] + __ldg(&conv_b[k]), 0.f);
        Xs[r * GW_STR + k]      = __float2half(xv);
        Xs[r * GW_STR + 64 + k] = __float2half(d_h[(size_t)(v0 + r) * D + k]);
    }
    __syncthreads();

    wmma::fragment<wmma::accumulator, 16, 16, 16, float> acc[8];
    #pragma unroll
    for (int f = 0; f < 8; f++) wmma::fill_fragment(acc[f], 0.f);

    #pragma unroll
    for (int kc = 0; kc < 8; kc++) {
        wmma::fragment<wmma::matrix_a, 16, 16, 16, __half, wmma::row_major> af[2];
        #pragma unroll
        for (int i = 0; i < 2; i++)
            wmma::load_matrix_sync(af[i], &Xs[(wm * 32 + i * 16) * GW_STR + kc * 16], GW_STR);
        #pragma unroll
        for (int nf = 0; nf < 4; nf++) {
            wmma::fragment<wmma::matrix_b, 16, 16, 16, __half, wmma::col_major> bf;
            wmma::load_matrix_sync(bf, &Wgs[(wn * 64 + nf * 16) * GW_STR + kc * 16], GW_STR);
            #pragma unroll
            for (int i = 0; i < 2; i++)
                wmma::mma_sync(acc[i * 4 + nf], af[i], bf, acc[i * 4 + nf]);
        }
    }

    __syncthreads();   // all warps done reading Wgs/Xs before overlay
    #pragma unroll
    for (int i = 0; i < 2; i++)
        #pragma unroll
        for (int nf = 0; nf < 4; nf++)
            wmma::store_matrix_sync(&Cs[(wm * 32 + i * 16) * GC_STR + wn * 64 + nf * 16],
                                    acc[i * 4 + nf], GC_STR, wmma::mem_row_major);
    __syncthreads();

    // fused gates: thread covers (node r, feature j); coalesced over tid
    for (int q = tid; q < 4096; q += 256) {
        int r = q >> 6, j = q & 63;
        int v = v0 + r;
        if (v >= V_N) break;
        const float* cr = Cs + r * GC_STR;
        float g0 = cr[j], g1 = cr[64 + j], g2 = cr[128 + j], g3 = cr[192 + j];
        float rg = 1.f / (1.f + expf(-(g0 + __ldg(&bih[j])      + __ldg(&bhh[j]))));
        float zg = 1.f / (1.f + expf(-(g1 + __ldg(&bih[64 + j]) + __ldg(&bhh[64 + j]))));
        float ng = tanhf(g2 + __ldg(&bih[128 + j]) + rg * (g3 + __ldg(&bhh[128 + j])));
        size_t gi = (size_t)v * D + j;
        float hp = d_h[gi];
        d_h[gi] = (1.f - zg) * ng + zg * hp;
        d_neigh[gi] = 0.f;
    }
}

__global__ void pred_kernel(const int* __restrict__ src, const int* __restrict__ dst,
                            const float* __restrict__ pW, const float* __restrict__ pb,
                            float* __restrict__ out) {
    int wg   = (blockIdx.x * blockDim.x + threadIdx.x) >> 5;
    int lane = threadIdx.x & 31;
    if (wg >= E_N) return;
    int se = src[wg], de = dst[wg];
    float2 a  = ((const float2*)(d_h + (size_t)se * D))[lane];
    float2 b  = ((const float2*)(d_h + (size_t)de * D))[lane];
    float2 w1 = ((const float2*)pW)[lane];
    float2 w2 = ((const float2*)pW)[32 + lane];
    float acc = a.x * w1.x + a.y * w1.y + b.x * w2.x + b.y * w2.y;
    #pragma unroll
    for (int off = 16; off > 0; off >>= 1)
        acc += __shfl_down_sync(0xffffffffu, acc, off);
    if (lane == 0) out[wg] = acc + pb[0];
}

// ---------------- launch ------------------------------------------------------
extern "C" void kernel_launch(void* const* d_in, const int* in_sizes, int n_in,
                              void* d_out, int out_size) {
    const float* node_feats = (const float*)d_in[0];
    const float* edge_feats = (const float*)d_in[1];
    const int*   src        = (const int*)d_in[2];
    const int*   dst        = (const int*)d_in[3];
    const float* proj_W     = (const float*)d_in[4];
    const float* proj_b     = (const float*)d_in[5];
    const float* en_W1      = (const float*)d_in[6];
    const float* en_b1      = (const float*)d_in[7];
    const float* en_W2      = (const float*)d_in[8];
    const float* en_b2      = (const float*)d_in[9];
    const float* conv_b     = (const float*)d_in[10];
    const float* gru_Wih    = (const float*)d_in[11];
    const float* gru_Whh    = (const float*)d_in[12];
    const float* gru_bih    = (const float*)d_in[13];
    const float* gru_bhh    = (const float*)d_in[14];
    const float* pred_W     = (const float*)d_in[15];
    const float* pred_b     = (const float*)d_in[16];
    float* out = (float*)d_out;

    static int attr_set = 0;
    if (!attr_set) {
        cudaFuncSetAttribute(ew_gemm, cudaFuncAttributeMaxDynamicSharedMemorySize, EW_SMEM);
        cudaFuncSetAttribute(gru_mm, cudaFuncAttributeMaxDynamicSharedMemorySize, GRU_SMEM);
        attr_set = 1;
    }

    proj_kernel<<<V_N / 16, 256>>>(node_feats, proj_W, proj_b);
    zhid_kernel<<<E_N / 16, 256>>>(edge_feats, en_W1, en_b1);
    prep_wg<<<(256 * EH + 255) / 256, 256>>>(gru_Wih, gru_Whh);
    dim3 gg(NSLABS, MGROUPS);                                            // (32, 4)
    ew_gemm<<<gg, 256, EW_SMEM>>>(en_W2, en_b2);
    zero_neigh<<<(V_PAD * D / 4 + 255) / 256, 256>>>();

    for (int s = 0; s < STEPS; s++) {
        scatter_kernel<<<E_N / 8, 256>>>(src, dst);
        gru_mm<<<V_PAD / 64, 256, GRU_SMEM>>>(conv_b, gru_bih, gru_bhh);
    }
    pred_kernel<<<E_N / 8, 256>>>(src, dst, pred_W, pred_b, out);
}

// round 7
// speedup vs baseline: 1.9055x; 1.0679x over previous
#include <cuda_runtime.h>
#include <cuda_fp16.h>
#include <mma.h>
#include <cstdint>

using namespace nvcuda;

#define V_N 20000
#define V_PAD 20032      // 313 * 64
#define E_N 40000
#define E_PAD 40064      // 313 * 128
#define NT 313           // 128-row M tiles in ew gemm
#define NIN 74
#define EIN 12
#define D 64
#define EH 128
#define DD 4096
#define STEPS 6

// ---------------- scratch (static device globals; zero-initialized) ---------
__device__ float  d_h[V_PAD * D];
__device__ float  d_neigh[V_PAD * D];
__device__ __half d_z[E_PAD * EH];
__device__ __half d_ew[(size_t)E_PAD * DD];
__device__ __half d_Wg[256 * EH];              // packed GRU weights (fp16)

// ---------------- cp.async helpers ------------------------------------------
__device__ __forceinline__ uint32_t smem_u32(const void* p) {
    uint32_t a;
    asm("{ .reg .u64 t; cvta.to.shared.u64 t, %1; cvt.u32.u64 %0, t; }" : "=r"(a) : "l"(p));
    return a;
}
__device__ __forceinline__ void cp16(uint32_t s, const void* g) {
    asm volatile("cp.async.cg.shared.global [%0], [%1], 16;" :: "r"(s), "l"(g));
}
#define CP_COMMIT() asm volatile("cp.async.commit_group;" ::: "memory")
#define CP_WAIT0()  asm volatile("cp.async.wait_group 0;" ::: "memory")

// ---------------- prep / small kernels ---------------------------------------
// pack GRU weights: Wg[256][128]; rows 0:64 [Wih_r|Whh_r], 64:128 [Wih_z|Whh_z],
// 128:192 [Wih_n|0], 192:256 [0|Whh_n]
__global__ void prep_wg(const float* __restrict__ Wih, const float* __restrict__ Whh) {
    int idx = blockIdx.x * blockDim.x + threadIdx.x;
    if (idx >= 256 * EH) return;
    int r = idx >> 7, k = idx & 127;
    float v = 0.f;
    if (r < 128) {
        v = (k < 64) ? Wih[r * D + k] : Whh[r * D + (k - 64)];
    } else if (r < 192) {                // i_n: Wih rows 128..191
        if (k < 64) v = Wih[r * D + k];
    } else {                             // h_n: Whh rows 128..191
        if (k >= 64) v = Whh[(r - 64) * D + (k - 64)];
    }
    d_Wg[idx] = __float2half(v);
}

__global__ void proj_kernel(const float* __restrict__ nf,
                            const float* __restrict__ W,
                            const float* __restrict__ b) {
    __shared__ float Ws[NIN][D];
    __shared__ float nfs[16][NIN + 2];
    __shared__ float bs[D];
    const int tid = threadIdx.x;
    const int v0 = blockIdx.x * 16;
    for (int idx = tid; idx < D * NIN; idx += 256) {
        int o = idx / NIN, i = idx % NIN;
        Ws[i][o] = W[idx];
    }
    for (int idx = tid; idx < 16 * NIN; idx += 256) {
        int n = idx / NIN, i = idx % NIN;
        nfs[n][i] = nf[(size_t)(v0 + n) * NIN + i];
    }
    if (tid < D) bs[tid] = b[tid];
    __syncthreads();
    const int o = tid & 63, g = tid >> 6;
    #pragma unroll
    for (int nn = 0; nn < 4; nn++) {
        int n = g * 4 + nn;
        float acc = bs[o];
        #pragma unroll
        for (int i = 0; i < NIN; i++) acc = fmaf(Ws[i][o], nfs[n][i], acc);
        d_h[(size_t)(v0 + n) * D + o] = fmaxf(acc, 0.f);
    }
}

__global__ void zhid_kernel(const float* __restrict__ ef,
                            const float* __restrict__ W1,
                            const float* __restrict__ b1) {
    __shared__ float W1s[EIN][EH];
    __shared__ float b1s[EH];
    __shared__ float efs[16][EIN];
    const int tid = threadIdx.x;
    const int e0 = blockIdx.x * 16;
    for (int idx = tid; idx < EH * EIN; idx += 256) {
        int k = idx / EIN, i = idx % EIN;
        W1s[i][k] = W1[idx];
    }
    for (int idx = tid; idx < 16 * EIN; idx += 256) {
        int e = idx / EIN, i = idx % EIN;
        efs[e][i] = ef[(size_t)(e0 + e) * EIN + i];
    }
    if (tid < EH) b1s[tid] = b1[tid];
    __syncthreads();
    const int k = tid & 127, g = tid >> 7;
    #pragma unroll
    for (int ee = 0; ee < 8; ee++) {
        int e = g * 8 + ee;
        float acc = b1s[k];
        #pragma unroll
        for (int i = 0; i < EIN; i++) acc = fmaf(W1s[i][k], efs[e][i], acc);
        d_z[(size_t)(e0 + e) * EH + k] = __float2half(fmaxf(acc, 0.f));
    }
}

// ---------------- ew GEMM (WMMA, bias folded into K) --------------------------
// C[E_PAD,4096] = [z|1] @ [W2|b2]^T ; A: (m x 144) fp16, B: (n x 144) fp16.
// Tile M=128 x N=128, K=144. Single-buffered A (next-tile cp.async overlaps
// epilogue; cross-CTA overlap from 2 CTAs/SM). 32-row C staging, 4 passes.
#define ASTR 152
#define BSTR 152
#define CSTR 132
#define B_BYTES   (128 * BSTR * 2)             // 38912
#define A_BYTES   (128 * ASTR * 2)             // 38912
#define A_OFF     B_BYTES
#define C_OFF     (A_OFF + A_BYTES)            // 77824
#define EW_SMEM   (C_OFF + 32 * CSTR * 4)      // 94720 -> 2 CTAs/SM
#define NSLABS 32
#define MGROUPS 9

__global__ __launch_bounds__(256, 2) void ew_gemm(const float* __restrict__ W2,
                                                  const float* __restrict__ b2) {
    extern __shared__ char smem[];
    __half* Bs = (__half*)smem;
    __half* As = (__half*)(smem + A_OFF);
    float*  Cs = (float*)(smem + C_OFF);
    const uint32_t sbase = smem_u32(smem);
    const int tid = threadIdx.x;
    const int w = tid >> 5;
    const int wm = w & 3;          // 4 M groups of 32 rows
    const int wn = w >> 2;         // 2 N groups of 64 cols
    const int n0 = blockIdx.x * 128;
    const int by = blockIdx.y;

    // B slab: 128 N-rows x 128 K (f32 -> f16) + bias col 128, zeros 129..143
    for (int q = tid; q < 4096; q += 256) {
        int n = q >> 5, k4 = (q & 31) * 4;
        float4 v = *(const float4*)&W2[(size_t)(n0 + n) * EH + k4];
        __half t4[4] = { __float2half(v.x), __float2half(v.y),
                         __float2half(v.z), __float2half(v.w) };
        *(uint2*)&Bs[n * BSTR + k4] = *(uint2*)t4;
    }
    for (int q = tid; q < 2048; q += 256) {
        int n = q >> 4, k = 128 + (q & 15);
        Bs[n * BSTR + k] = (k == 128) ? __float2half(b2[n0 + n]) : __half(0);
    }
    // A constant tail: col 128 = 1, 129..143 = 0 (cp.async only writes cols<128)
    for (int q = tid; q < 2048; q += 256) {
        int r = q >> 4, k = 128 + (q & 15);
        As[r * ASTR + k] = (k == 128) ? __float2half(1.f) : __half(0);
    }
    // prefetch first A tile
    for (int q = tid; q < 2048; q += 256) {
        int r = q >> 4, c = (q & 15) * 8;
        cp16(sbase + A_OFF + (uint32_t)(r * ASTR + c) * 2,
             &d_z[(size_t)(by * 128 + r) * EH + c]);
    }
    CP_COMMIT();

    const int TPT = (NT + MGROUPS - 1) / MGROUPS;
    for (int mt = 0; mt < TPT; mt++) {
        int t = by + MGROUPS * mt;
        if (t >= NT) break;
        CP_WAIT0();
        __syncthreads();                      // A ready for all warps

        wmma::fragment<wmma::accumulator, 16, 16, 16, float> acc[8];
        #pragma unroll
        for (int f = 0; f < 8; f++) wmma::fill_fragment(acc[f], 0.f);

        #pragma unroll
        for (int kc = 0; kc < 9; kc++) {
            wmma::fragment<wmma::matrix_a, 16, 16, 16, __half, wmma::row_major> af[2];
            #pragma unroll
            for (int i = 0; i < 2; i++)
                wmma::load_matrix_sync(af[i], &As[(wm * 32 + i * 16) * ASTR + kc * 16], ASTR);
            #pragma unroll
            for (int nf = 0; nf < 4; nf++) {
                wmma::fragment<wmma::matrix_b, 16, 16, 16, __half, wmma::col_major> bf;
                wmma::load_matrix_sync(bf, &Bs[(wn * 64 + nf * 16) * BSTR + kc * 16], BSTR);
                #pragma unroll
                for (int i = 0; i < 2; i++)
                    wmma::mma_sync(acc[i * 4 + nf], af[i], bf, acc[i * 4 + nf]);
            }
        }
        __syncthreads();                      // all warps done reading A

        int tn = t + MGROUPS;                 // prefetch next (overlaps epilogue)
        if (tn < NT) {
            for (int q = tid; q < 2048; q += 256) {
                int r = q >> 4, c = (q & 15) * 8;
                cp16(sbase + A_OFF + (uint32_t)(r * ASTR + c) * 2,
                     &d_z[(size_t)(tn * 128 + r) * EH + c]);
            }
            CP_COMMIT();
        }

        // epilogue: 4 passes of 32 rows through Cs
        #pragma unroll
        for (int p = 0; p < 4; p++) {
            if (p) __syncthreads();           // prev pass's Cs reads done
            if (wm == p) {
                #pragma unroll
                for (int i = 0; i < 2; i++)
                    #pragma unroll
                    for (int nf = 0; nf < 4; nf++)
                        wmma::store_matrix_sync(&Cs[(i * 16) * CSTR + wn * 64 + nf * 16],
                                                acc[i * 4 + nf], CSTR, wmma::mem_row_major);
            }
            __syncthreads();
            for (int q = tid; q < 512; q += 256) {     // 32 rows x 16 int4
                int r = q >> 4, c8 = (q & 15) * 8;
                __half tmp[8];
                #pragma unroll
                for (int j = 0; j < 8; j++)
                    tmp[j] = __float2half(Cs[r * CSTR + c8 + j]);
                *(int4*)&d_ew[(size_t)(t * 128 + p * 32 + r) * DD + n0 + c8] = *(int4*)tmp;
            }
        }
    }
}

// ---------------- per-step kernels -------------------------------------------
__global__ void zero_neigh() {
    int idx = blockIdx.x * blockDim.x + threadIdx.x;
    if (idx < V_PAD * D / 4)
        ((float4*)d_neigh)[idx] = make_float4(0.f, 0.f, 0.f, 0.f);
}

// warp per edge, LDG.128 rows: iter i covers rows 4i..4i+3 (512B coalesced)
__global__ void scatter_kernel(const int* __restrict__ src, const int* __restrict__ dst) {
    int wg   = (blockIdx.x * blockDim.x + threadIdx.x) >> 5;
    int lane = threadIdx.x & 31;
    if (wg >= E_N) return;
    int se = __ldg(&src[wg]), de = __ldg(&dst[wg]);
    float2 hv = ((const float2*)(d_h + (size_t)se * D))[lane];
    const int4* W4 = (const int4*)(d_ew + (size_t)wg * DD);   // 8 int4 per 64-half row
    const int rsub = lane >> 3;        // row-subgroup 0..3
    const int cg   = lane & 7;         // col group: cols 8*cg..8*cg+7
    float acc[8] = {0.f, 0.f, 0.f, 0.f, 0.f, 0.f, 0.f, 0.f};

    #pragma unroll
    for (int i = 0; i < 16; i++) {
        int r = 4 * i + rsub;
        int4 wv = __ldg(&W4[r * 8 + cg]);
        float hx = __shfl_sync(0xffffffffu, hv.x, 2 * i + (lane >> 4));
        float hy = __shfl_sync(0xffffffffu, hv.y, 2 * i + (lane >> 4));
        float hr = (rsub & 1) ? hy : hx;
        const __half2* wh = (const __half2*)&wv;
        #pragma unroll
        for (int q = 0; q < 4; q++) {
            float2 f = __half22float2(wh[q]);
            acc[2 * q]     = fmaf(hr, f.x, acc[2 * q]);
            acc[2 * q + 1] = fmaf(hr, f.y, acc[2 * q + 1]);
        }
    }
    #pragma unroll
    for (int j = 0; j < 8; j++) {
        acc[j] += __shfl_xor_sync(0xffffffffu, acc[j], 8);
        acc[j] += __shfl_xor_sync(0xffffffffu, acc[j], 16);
    }
    if (lane < 8) {
        float* nb = d_neigh + (size_t)de * D + lane * 8;
        #pragma unroll
        for (int j = 0; j < 8; j++) atomicAdd(nb + j, acc[j]);
    }
}

// GRU: G = [relu(neigh+cb) | h](fp16) @ Wg^T (fp32 accum), fused gates +
// h update + neigh re-zero. block 256 thr, tile M=64 nodes x N=256 gate-rows.
#define GW_STR 136
#define GC_STR 264
#define GX_OFF (256 * GW_STR * 2)              // 69632
#define GRU_SMEM (GX_OFF + 64 * GW_STR * 2)    // 87040 (Cs 64x264x4 overlays Wgs)
__global__ __launch_bounds__(256, 2) void gru_mm(const float* __restrict__ conv_b,
                                                 const float* __restrict__ bih,
                                                 const float* __restrict__ bhh) {
    extern __shared__ char smem[];
    __half* Wgs = (__half*)smem;
    __half* Xs  = (__half*)(smem + GX_OFF);
    float*  Cs  = (float*)smem;                // overlay after MMA
    const int tid = threadIdx.x;
    const int w = tid >> 5;
    const int wm = w & 1;
    const int wn = w >> 1;
    const int v0 = blockIdx.x * 64;

    for (int q = tid; q < 4096; q += 256) {
        int r = q >> 4, c8 = (q & 15) * 8;
        *(int4*)&Wgs[r * GW_STR + c8] = *(const int4*)&d_Wg[r * EH + c8];
    }
    for (int q = tid; q < 4096; q += 256) {
        int r = q >> 6, k = q & 63;
        float xv = fmaxf(d_neigh[(size_t)(v0 + r) * D + k] + __ldg(&conv_b[k]), 0.f);
        Xs[r * GW_STR + k]      = __float2half(xv);
        Xs[r * GW_STR + 64 + k] = __float2half(d_h[(size_t)(v0 + r) * D + k]);
    }
    __syncthreads();

    wmma::fragment<wmma::accumulator, 16, 16, 16, float> acc[8];
    #pragma unroll
    for (int f = 0; f < 8; f++) wmma::fill_fragment(acc[f], 0.f);

    #pragma unroll
    for (int kc = 0; kc < 8; kc++) {
        wmma::fragment<wmma::matrix_a, 16, 16, 16, __half, wmma::row_major> af[2];
        #pragma unroll
        for (int i = 0; i < 2; i++)
            wmma::load_matrix_sync(af[i], &Xs[(wm * 32 + i * 16) * GW_STR + kc * 16], GW_STR);
        #pragma unroll
        for (int nf = 0; nf < 4; nf++) {
            wmma::fragment<wmma::matrix_b, 16, 16, 16, __half, wmma::col_major> bf;
            wmma::load_matrix_sync(bf, &Wgs[(wn * 64 + nf * 16) * GW_STR + kc * 16], GW_STR);
            #pragma unroll
            for (int i = 0; i < 2; i++)
                wmma::mma_sync(acc[i * 4 + nf], af[i], bf, acc[i * 4 + nf]);
        }
    }

    __syncthreads();
    #pragma unroll
    for (int i = 0; i < 2; i++)
        #pragma unroll
        for (int nf = 0; nf < 4; nf++)
            wmma::store_matrix_sync(&Cs[(wm * 32 + i * 16) * GC_STR + wn * 64 + nf * 16],
                                    acc[i * 4 + nf], GC_STR, wmma::mem_row_major);
    __syncthreads();

    for (int q = tid; q < 4096; q += 256) {
        int r = q >> 6, j = q & 63;
        int v = v0 + r;
        if (v >= V_N) break;
        const float* cr = Cs + r * GC_STR;
        float g0 = cr[j], g1 = cr[64 + j], g2 = cr[128 + j], g3 = cr[192 + j];
        float rg = 1.f / (1.f + expf(-(g0 + __ldg(&bih[j])      + __ldg(&bhh[j]))));
        float zg = 1.f / (1.f + expf(-(g1 + __ldg(&bih[64 + j]) + __ldg(&bhh[64 + j]))));
        float ng = tanhf(g2 + __ldg(&bih[128 + j]) + rg * (g3 + __ldg(&bhh[128 + j])));
        size_t gi = (size_t)v * D + j;
        float hp = d_h[gi];
        d_h[gi] = (1.f - zg) * ng + zg * hp;
        d_neigh[gi] = 0.f;
    }
}

__global__ void pred_kernel(const int* __restrict__ src, const int* __restrict__ dst,
                            const float* __restrict__ pW, const float* __restrict__ pb,
                            float* __restrict__ out) {
    int wg   = (blockIdx.x * blockDim.x + threadIdx.x) >> 5;
    int lane = threadIdx.x & 31;
    if (wg >= E_N) return;
    int se = src[wg], de = dst[wg];
    float2 a  = ((const float2*)(d_h + (size_t)se * D))[lane];
    float2 b  = ((const float2*)(d_h + (size_t)de * D))[lane];
    float2 w1 = ((const float2*)pW)[lane];
    float2 w2 = ((const float2*)pW)[32 + lane];
    float acc = a.x * w1.x + a.y * w1.y + b.x * w2.x + b.y * w2.y;
    #pragma unroll
    for (int off = 16; off > 0; off >>= 1)
        acc += __shfl_down_sync(0xffffffffu, acc, off);
    if (lane == 0) out[wg] = acc + pb[0];
}

// ---------------- launch ------------------------------------------------------
extern "C" void kernel_launch(void* const* d_in, const int* in_sizes, int n_in,
                              void* d_out, int out_size) {
    const float* node_feats = (const float*)d_in[0];
    const float* edge_feats = (const float*)d_in[1];
    const int*   src        = (const int*)d_in[2];
    const int*   dst        = (const int*)d_in[3];
    const float* proj_W     = (const float*)d_in[4];
    const float* proj_b     = (const float*)d_in[5];
    const float* en_W1      = (const float*)d_in[6];
    const float* en_b1      = (const float*)d_in[7];
    const float* en_W2      = (const float*)d_in[8];
    const float* en_b2      = (const float*)d_in[9];
    const float* conv_b     = (const float*)d_in[10];
    const float* gru_Wih    = (const float*)d_in[11];
    const float* gru_Whh    = (const float*)d_in[12];
    const float* gru_bih    = (const float*)d_in[13];
    const float* gru_bhh    = (const float*)d_in[14];
    const float* pred_W     = (const float*)d_in[15];
    const float* pred_b     = (const float*)d_in[16];
    float* out = (float*)d_out;

    static int attr_set = 0;
    if (!attr_set) {
        cudaFuncSetAttribute(ew_gemm, cudaFuncAttributeMaxDynamicSharedMemorySize, EW_SMEM);
        cudaFuncSetAttribute(gru_mm, cudaFuncAttributeMaxDynamicSharedMemorySize, GRU_SMEM);
        attr_set = 1;
    }

    proj_kernel<<<V_N / 16, 256>>>(node_feats, proj_W, proj_b);
    zhid_kernel<<<E_N / 16, 256>>>(edge_feats, en_W1, en_b1);
    prep_wg<<<(256 * EH + 255) / 256, 256>>>(gru_Wih, gru_Whh);
    dim3 gg(NSLABS, MGROUPS);                                            // (32, 9)
    ew_gemm<<<gg, 256, EW_SMEM>>>(en_W2, en_b2);
    zero_neigh<<<(V_PAD * D / 4 + 255) / 256, 256>>>();

    for (int s = 0; s < STEPS; s++) {
        scatter_kernel<<<E_N / 8, 256>>>(src, dst);
        gru_mm<<<V_PAD / 64, 256, GRU_SMEM>>>(conv_b, gru_bih, gru_bhh);
    }
    pred_kernel<<<E_N / 8, 256>>>(src, dst, pred_W, pred_b, out);
}

// round 8
// speedup vs baseline: 1.9290x; 1.0124x over previous
#include <cuda_runtime.h>
#include <cuda_fp16.h>
#include <cstdint>

#define V_N 20000
#define V_PAD 20032      // 313 * 64
#define E_N 40000
#define E_PAD 40064      // 313 * 128
#define NT 313           // 128-row M tiles in ew gemm
#define NIN 74
#define EIN 12
#define D 64
#define EH 128
#define DD 4096
#define STEPS 6

// ---------------- scratch (static device globals; zero-initialized) ---------
__device__ float  d_h[V_PAD * D];
__device__ float  d_neigh[V_PAD * D];
__device__ __half d_z[E_PAD * EH];
__device__ __half d_ew[(size_t)E_PAD * DD];
__device__ __half d_Wg[256 * EH];              // packed GRU weights (fp16)

// ---------------- asm helpers -------------------------------------------------
__device__ __forceinline__ uint32_t smem_u32(const void* p) {
    uint32_t a;
    asm("{ .reg .u64 t; cvta.to.shared.u64 t, %1; cvt.u32.u64 %0, t; }" : "=r"(a) : "l"(p));
    return a;
}
__device__ __forceinline__ void cp16(uint32_t s, const void* g) {
    asm volatile("cp.async.cg.shared.global [%0], [%1], 16;" :: "r"(s), "l"(g));
}
#define CP_COMMIT() asm volatile("cp.async.commit_group;" ::: "memory")
#define CP_WAIT0()  asm volatile("cp.async.wait_group 0;" ::: "memory")

__device__ __forceinline__ void ldsm_x4(uint32_t addr, uint32_t& r0, uint32_t& r1,
                                        uint32_t& r2, uint32_t& r3) {
    asm volatile("ldmatrix.sync.aligned.m8n8.x4.shared.b16 {%0,%1,%2,%3}, [%4];"
                 : "=r"(r0), "=r"(r1), "=r"(r2), "=r"(r3) : "r"(addr));
}
__device__ __forceinline__ void ldsm_x2(uint32_t addr, uint32_t& r0, uint32_t& r1) {
    asm volatile("ldmatrix.sync.aligned.m8n8.x2.shared.b16 {%0,%1}, [%2];"
                 : "=r"(r0), "=r"(r1) : "r"(addr));
}
__device__ __forceinline__ void mma16816(float* c, const uint32_t* a, const uint32_t* b) {
    asm volatile("mma.sync.aligned.m16n8k16.row.col.f32.f16.f16.f32 "
                 "{%0,%1,%2,%3}, {%4,%5,%6,%7}, {%8,%9}, {%0,%1,%2,%3};"
                 : "+f"(c[0]), "+f"(c[1]), "+f"(c[2]), "+f"(c[3])
                 : "r"(a[0]), "r"(a[1]), "r"(a[2]), "r"(a[3]), "r"(b[0]), "r"(b[1]));
}

// ---------------- prep / small kernels ---------------------------------------
// pack GRU weights: Wg[256][128]; rows 0:64 [Wih_r|Whh_r], 64:128 [Wih_z|Whh_z],
// 128:192 [Wih_n|0], 192:256 [0|Whh_n]
__global__ void prep_wg(const float* __restrict__ Wih, const float* __restrict__ Whh) {
    int idx = blockIdx.x * blockDim.x + threadIdx.x;
    if (idx >= 256 * EH) return;
    int r = idx >> 7, k = idx & 127;
    float v = 0.f;
    if (r < 128) {
        v = (k < 64) ? Wih[r * D + k] : Whh[r * D + (k - 64)];
    } else if (r < 192) {                // i_n: Wih rows 128..191
        if (k < 64) v = Wih[r * D + k];
    } else {                             // h_n: Whh rows 128..191
        if (k >= 64) v = Whh[(r - 64) * D + (k - 64)];
    }
    d_Wg[idx] = __float2half(v);
}

__global__ void proj_kernel(const float* __restrict__ nf,
                            const float* __restrict__ W,
                            const float* __restrict__ b) {
    __shared__ float Ws[NIN][D];
    __shared__ float nfs[16][NIN + 2];
    __shared__ float bs[D];
    const int tid = threadIdx.x;
    const int v0 = blockIdx.x * 16;
    for (int idx = tid; idx < D * NIN; idx += 256) {
        int o = idx / NIN, i = idx % NIN;
        Ws[i][o] = W[idx];
    }
    for (int idx = tid; idx < 16 * NIN; idx += 256) {
        int n = idx / NIN, i = idx % NIN;
        nfs[n][i] = nf[(size_t)(v0 + n) * NIN + i];
    }
    if (tid < D) bs[tid] = b[tid];
    __syncthreads();
    const int o = tid & 63, g = tid >> 6;
    #pragma unroll
    for (int nn = 0; nn < 4; nn++) {
        int n = g * 4 + nn;
        float acc = bs[o];
        #pragma unroll
        for (int i = 0; i < NIN; i++) acc = fmaf(Ws[i][o], nfs[n][i], acc);
        d_h[(size_t)(v0 + n) * D + o] = fmaxf(acc, 0.f);
    }
}

__global__ void zhid_kernel(const float* __restrict__ ef,
                            const float* __restrict__ W1,
                            const float* __restrict__ b1) {
    __shared__ float W1s[EIN][EH];
    __shared__ float b1s[EH];
    __shared__ float efs[16][EIN];
    const int tid = threadIdx.x;
    const int e0 = blockIdx.x * 16;
    for (int idx = tid; idx < EH * EIN; idx += 256) {
        int k = idx / EIN, i = idx % EIN;
        W1s[i][k] = W1[idx];
    }
    for (int idx = tid; idx < 16 * EIN; idx += 256) {
        int e = idx / EIN, i = idx % EIN;
        efs[e][i] = ef[(size_t)(e0 + e) * EIN + i];
    }
    if (tid < EH) b1s[tid] = b1[tid];
    __syncthreads();
    const int k = tid & 127, g = tid >> 7;
    #pragma unroll
    for (int ee = 0; ee < 8; ee++) {
        int e = g * 8 + ee;
        float acc = b1s[k];
        #pragma unroll
        for (int i = 0; i < EIN; i++) acc = fmaf(W1s[i][k], efs[e][i], acc);
        d_z[(size_t)(e0 + e) * EH + k] = __float2half(fmaxf(acc, 0.f));
    }
}

// ---------------- ew GEMM (PTX mma, direct-register epilogue) -----------------
// C[E_PAD,4096] = [z|1] @ [W2|b2]^T ; A: (m x 144) fp16, B: (n x 144) fp16.
// Tile M=128 x N=128, K=144 (9 k16 chunks; chunk 8 = bias fold).
// Warp tile 32(M) x 64(N): 2 m16 x 8 n8 frags. Accum -> half2 STG direct.
#define ASTR 152
#define BSTR 152
#define B_BYTES   (128 * BSTR * 2)             // 38912
#define A_BYTES   (128 * ASTR * 2)             // 38912
#define A_OFF     B_BYTES
#define EW_SMEM   (A_OFF + A_BYTES)            // 77824 -> 2 CTAs/SM
#define NSLABS 32
#define MGROUPS 9

__global__ __launch_bounds__(256, 2) void ew_gemm(const float* __restrict__ W2,
                                                  const float* __restrict__ b2) {
    extern __shared__ char smem[];
    __half* Bs = (__half*)smem;
    __half* As = (__half*)(smem + A_OFF);
    const uint32_t sbase = smem_u32(smem);
    const int tid  = threadIdx.x;
    const int lane = tid & 31;
    const int w    = tid >> 5;
    const int wm   = w & 3;        // 4 M groups of 32 rows
    const int wn   = w >> 2;       // 2 N groups of 64 cols
    const int n0   = blockIdx.x * 128;
    const int by   = blockIdx.y;

    // B slab: 128 N-rows x 128 K (f32 -> f16) + bias col 128, zeros 129..143
    for (int q = tid; q < 4096; q += 256) {
        int n = q >> 5, k4 = (q & 31) * 4;
        float4 v = *(const float4*)&W2[(size_t)(n0 + n) * EH + k4];
        __half t4[4] = { __float2half(v.x), __float2half(v.y),
                         __float2half(v.z), __float2half(v.w) };
        *(uint2*)&Bs[n * BSTR + k4] = *(uint2*)t4;
    }
    for (int q = tid; q < 2048; q += 256) {
        int n = q >> 4, k = 128 + (q & 15);
        Bs[n * BSTR + k] = (k == 128) ? __float2half(b2[n0 + n]) : __half(0);
    }
    // A constant tail: col 128 = 1, 129..143 = 0 (cp.async only writes cols<128)
    for (int q = tid; q < 2048; q += 256) {
        int r = q >> 4, k = 128 + (q & 15);
        As[r * ASTR + k] = (k == 128) ? __float2half(1.f) : __half(0);
    }
    // prefetch first A tile
    for (int q = tid; q < 2048; q += 256) {
        int r = q >> 4, c = (q & 15) * 8;
        cp16(sbase + A_OFF + (uint32_t)(r * ASTR + c) * 2,
             &d_z[(size_t)(by * 128 + r) * EH + c]);
    }
    CP_COMMIT();

    // ldmatrix per-lane base offsets (element units)
    const int a_r = lane & 15, a_c = (lane >> 4) * 8;            // A x4
    const int b_r = lane & 7,  b_c = ((lane >> 3) & 1) * 8;      // B x2
    const uint32_t aAddr0 = sbase + A_OFF + (uint32_t)((wm * 32 + a_r) * ASTR + a_c) * 2;
    const uint32_t bAddr0 = sbase + (uint32_t)((wn * 64 + b_r) * BSTR + b_c) * 2;

    const int TPT = (NT + MGROUPS - 1) / MGROUPS;
    for (int mt = 0; mt < TPT; mt++) {
        int t = by + MGROUPS * mt;
        if (t >= NT) break;
        CP_WAIT0();
        __syncthreads();                      // A ready for all warps

        float c[2][8][4];
        #pragma unroll
        for (int i = 0; i < 2; i++)
            #pragma unroll
            for (int j = 0; j < 8; j++)
                #pragma unroll
                for (int q = 0; q < 4; q++) c[i][j][q] = 0.f;

        #pragma unroll
        for (int kc = 0; kc < 9; kc++) {
            uint32_t a[2][4];
            #pragma unroll
            for (int i = 0; i < 2; i++)
                ldsm_x4(aAddr0 + (uint32_t)(i * 16 * ASTR + kc * 16) * 2,
                        a[i][0], a[i][1], a[i][2], a[i][3]);
            uint32_t b[8][2];
            #pragma unroll
            for (int j = 0; j < 8; j++)
                ldsm_x2(bAddr0 + (uint32_t)(j * 8 * BSTR + kc * 16) * 2,
                        b[j][0], b[j][1]);
            #pragma unroll
            for (int i = 0; i < 2; i++)
                #pragma unroll
                for (int j = 0; j < 8; j++)
                    mma16816(c[i][j], a[i], b[j]);
        }
        __syncthreads();                      // all warps done reading A

        int tn = t + MGROUPS;                 // prefetch next (overlaps epilogue)
        if (tn < NT) {
            for (int q = tid; q < 2048; q += 256) {
                int r = q >> 4, cc = (q & 15) * 8;
                cp16(sbase + A_OFF + (uint32_t)(r * ASTR + cc) * 2,
                     &d_z[(size_t)(tn * 128 + r) * EH + cc]);
            }
            CP_COMMIT();
        }

        // direct epilogue: thread owns rows (base, base+8), col pair 2*(lane&3)
        const int rbase = t * 128 + wm * 32 + (lane >> 2);
        const int cbase = n0 + wn * 64 + 2 * (lane & 3);
        #pragma unroll
        for (int i = 0; i < 2; i++) {
            size_t rowo = (size_t)(rbase + i * 16) * DD;
            #pragma unroll
            for (int j = 0; j < 8; j++) {
                int col = cbase + j * 8;
                *(__half2*)&d_ew[rowo + col] =
                    __floats2half2_rn(c[i][j][0], c[i][j][1]);
                *(__half2*)&d_ew[rowo + 8 * DD + col] =
                    __floats2half2_rn(c[i][j][2], c[i][j][3]);
            }
        }
    }
}

// ---------------- per-step kernels -------------------------------------------
__global__ void zero_neigh() {
    int idx = blockIdx.x * blockDim.x + threadIdx.x;
    if (idx < V_PAD * D / 4)
        ((float4*)d_neigh)[idx] = make_float4(0.f, 0.f, 0.f, 0.f);
}

// warp per edge, LDG.128 rows: iter i covers rows 4i..4i+3 (512B coalesced)
__global__ void scatter_kernel(const int* __restrict__ src, const int* __restrict__ dst) {
    int wg   = (blockIdx.x * blockDim.x + threadIdx.x) >> 5;
    int lane = threadIdx.x & 31;
    if (wg >= E_N) return;
    int se = __ldg(&src[wg]), de = __ldg(&dst[wg]);
    float2 hv = ((const float2*)(d_h + (size_t)se * D))[lane];
    const int4* W4 = (const int4*)(d_ew + (size_t)wg * DD);
    const int rsub = lane >> 3;
    const int cg   = lane & 7;
    float acc[8] = {0.f, 0.f, 0.f, 0.f, 0.f, 0.f, 0.f, 0.f};

    #pragma unroll
    for (int i = 0; i < 16; i++) {
        int r = 4 * i + rsub;
        int4 wv = __ldg(&W4[r * 8 + cg]);
        float hx = __shfl_sync(0xffffffffu, hv.x, 2 * i + (lane >> 4));
        float hy = __shfl_sync(0xffffffffu, hv.y, 2 * i + (lane >> 4));
        float hr = (rsub & 1) ? hy : hx;
        const __half2* wh = (const __half2*)&wv;
        #pragma unroll
        for (int q = 0; q < 4; q++) {
            float2 f = __half22float2(wh[q]);
            acc[2 * q]     = fmaf(hr, f.x, acc[2 * q]);
            acc[2 * q + 1] = fmaf(hr, f.y, acc[2 * q + 1]);
        }
    }
    #pragma unroll
    for (int j = 0; j < 8; j++) {
        acc[j] += __shfl_xor_sync(0xffffffffu, acc[j], 8);
        acc[j] += __shfl_xor_sync(0xffffffffu, acc[j], 16);
    }
    if (lane < 8) {
        float* nb = d_neigh + (size_t)de * D + lane * 8;
        #pragma unroll
        for (int j = 0; j < 8; j++) atomicAdd(nb + j, acc[j]);
    }
}

// GRU: G = [relu(neigh+cb) | h](fp16) @ Wg^T (fp32 accum), fused gates +
// h update + neigh re-zero. block 256 thr, tile M=64 nodes x N=256 gate-rows.
#include <mma.h>
using namespace nvcuda;
#define GW_STR 136
#define GC_STR 264
#define GX_OFF (256 * GW_STR * 2)              // 69632
#define GRU_SMEM (GX_OFF + 64 * GW_STR * 2)    // 87040 (Cs 64x264x4 overlays Wgs)
__global__ __launch_bounds__(256, 2) void gru_mm(const float* __restrict__ conv_b,
                                                 const float* __restrict__ bih,
                                                 const float* __restrict__ bhh) {
    extern __shared__ char smem[];
    __half* Wgs = (__half*)smem;
    __half* Xs  = (__half*)(smem + GX_OFF);
    float*  Cs  = (float*)smem;                // overlay after MMA
    const int tid = threadIdx.x;
    const int w = tid >> 5;
    const int wm = w & 1;
    const int wn = w >> 1;
    const int v0 = blockIdx.x * 64;

    for (int q = tid; q < 4096; q += 256) {
        int r = q >> 4, c8 = (q & 15) * 8;
        *(int4*)&Wgs[r * GW_STR + c8] = *(const int4*)&d_Wg[r * EH + c8];
    }
    for (int q = tid; q < 4096; q += 256) {
        int r = q >> 6, k = q & 63;
        float xv = fmaxf(d_neigh[(size_t)(v0 + r) * D + k] + __ldg(&conv_b[k]), 0.f);
        Xs[r * GW_STR + k]      = __float2half(xv);
        Xs[r * GW_STR + 64 + k] = __float2half(d_h[(size_t)(v0 + r) * D + k]);
    }
    __syncthreads();

    wmma::fragment<wmma::accumulator, 16, 16, 16, float> acc[8];
    #pragma unroll
    for (int f = 0; f < 8; f++) wmma::fill_fragment(acc[f], 0.f);

    #pragma unroll
    for (int kc = 0; kc < 8; kc++) {
        wmma::fragment<wmma::matrix_a, 16, 16, 16, __half, wmma::row_major> af[2];
        #pragma unroll
        for (int i = 0; i < 2; i++)
            wmma::load_matrix_sync(af[i], &Xs[(wm * 32 + i * 16) * GW_STR + kc * 16], GW_STR);
        #pragma unroll
        for (int nf = 0; nf < 4; nf++) {
            wmma::fragment<wmma::matrix_b, 16, 16, 16, __half, wmma::col_major> bf;
            wmma::load_matrix_sync(bf, &Wgs[(wn * 64 + nf * 16) * GW_STR + kc * 16], GW_STR);
            #pragma unroll
            for (int i = 0; i < 2; i++)
                wmma::mma_sync(acc[i * 4 + nf], af[i], bf, acc[i * 4 + nf]);
        }
    }

    __syncthreads();
    #pragma unroll
    for (int i = 0; i < 2; i++)
        #pragma unroll
        for (int nf = 0; nf < 4; nf++)
            wmma::store_matrix_sync(&Cs[(wm * 32 + i * 16) * GC_STR + wn * 64 + nf * 16],
                                    acc[i * 4 + nf], GC_STR, wmma::mem_row_major);
    __syncthreads();

    for (int q = tid; q < 4096; q += 256) {
        int r = q >> 6, j = q & 63;
        int v = v0 + r;
        if (v >= V_N) break;
        const float* cr = Cs + r * GC_STR;
        float g0 = cr[j], g1 = cr[64 + j], g2 = cr[128 + j], g3 = cr[192 + j];
        float rg = 1.f / (1.f + expf(-(g0 + __ldg(&bih[j])      + __ldg(&bhh[j]))));
        float zg = 1.f / (1.f + expf(-(g1 + __ldg(&bih[64 + j]) + __ldg(&bhh[64 + j]))));
        float ng = tanhf(g2 + __ldg(&bih[128 + j]) + rg * (g3 + __ldg(&bhh[128 + j])));
        size_t gi = (size_t)v * D + j;
        float hp = d_h[gi];
        d_h[gi] = (1.f - zg) * ng + zg * hp;
        d_neigh[gi] = 0.f;
    }
}

__global__ void pred_kernel(const int* __restrict__ src, const int* __restrict__ dst,
                            const float* __restrict__ pW, const float* __restrict__ pb,
                            float* __restrict__ out) {
    int wg   = (blockIdx.x * blockDim.x + threadIdx.x) >> 5;
    int lane = threadIdx.x & 31;
    if (wg >= E_N) return;
    int se = src[wg], de = dst[wg];
    float2 a  = ((const float2*)(d_h + (size_t)se * D))[lane];
    float2 b  = ((const float2*)(d_h + (size_t)de * D))[lane];
    float2 w1 = ((const float2*)pW)[lane];
    float2 w2 = ((const float2*)pW)[32 + lane];
    float acc = a.x * w1.x + a.y * w1.y + b.x * w2.x + b.y * w2.y;
    #pragma unroll
    for (int off = 16; off > 0; off >>= 1)
        acc += __shfl_down_sync(0xffffffffu, acc, off);
    if (lane == 0) out[wg] = acc + pb[0];
}

// ---------------- launch ------------------------------------------------------
extern "C" void kernel_launch(void* const* d_in, const int* in_sizes, int n_in,
                              void* d_out, int out_size) {
    const float* node_feats = (const float*)d_in[0];
    const float* edge_feats = (const float*)d_in[1];
    const int*   src        = (const int*)d_in[2];
    const int*   dst        = (const int*)d_in[3];
    const float* proj_W     = (const float*)d_in[4];
    const float* proj_b     = (const float*)d_in[5];
    const float* en_W1      = (const float*)d_in[6];
    const float* en_b1      = (const float*)d_in[7];
    const float* en_W2      = (const float*)d_in[8];
    const float* en_b2      = (const float*)d_in[9];
    const float* conv_b     = (const float*)d_in[10];
    const float* gru_Wih    = (const float*)d_in[11];
    const float* gru_Whh    = (const float*)d_in[12];
    const float* gru_bih    = (const float*)d_in[13];
    const float* gru_bhh    = (const float*)d_in[14];
    const float* pred_W     = (const float*)d_in[15];
    const float* pred_b     = (const float*)d_in[16];
    float* out = (float*)d_out;

    static int attr_set = 0;
    if (!attr_set) {
        cudaFuncSetAttribute(ew_gemm, cudaFuncAttributeMaxDynamicSharedMemorySize, EW_SMEM);
        cudaFuncSetAttribute(gru_mm, cudaFuncAttributeMaxDynamicSharedMemorySize, GRU_SMEM);
        attr_set = 1;
    }

    proj_kernel<<<V_N / 16, 256>>>(node_feats, proj_W, proj_b);
    zhid_kernel<<<E_N / 16, 256>>>(edge_feats, en_W1, en_b1);
    prep_wg<<<(256 * EH + 255) / 256, 256>>>(gru_Wih, gru_Whh);
    dim3 gg(NSLABS, MGROUPS);                                            // (32, 9)
    ew_gemm<<<gg, 256, EW_SMEM>>>(en_W2, en_b2);
    zero_neigh<<<(V_PAD * D / 4 + 255) / 256, 256>>>();

    for (int s = 0; s < STEPS; s++) {
        scatter_kernel<<<E_N / 8, 256>>>(src, dst);
        gru_mm<<<V_PAD / 64, 256, GRU_SMEM>>>(conv_b, gru_bih, gru_bhh);
    }
    pred_kernel<<<E_N / 8, 256>>>(src, dst, pred_W, pred_b, out);
}